// round 5
// baseline (speedup 1.0000x reference)
#include <cuda_runtime.h>
#include <math.h>
#include <stdint.h>

// Problem shape (fixed by the reference): B=64, T=2048, D=U=256.
#define B_     64
#define T_     2048
#define D_     256
#define NCHUNK 4                 // T-chunks per batch row
#define TCHUNK (T_ / NCHUNK)     // 512 t-rows per block
#define TSUB   32                // rows per SMEM subtile
#define NSUB   (TCHUNK / TSUB)   // 16 subtiles

// Scratch (allocation-free rule -> __device__ globals)
__device__ float g_w[D_];                       // w = W @ v
__device__ float g_pm[B_ * NCHUNK];             // per-chunk running max
__device__ float g_pz[B_ * NCHUNK];             // per-chunk running sum(exp)
__device__ float g_pacc[B_ * NCHUNK * D_];      // per-chunk weighted accumulators
__device__ unsigned g_cnt[B_];                  // per-b arrival counters (zero-init)

// ---------------------------------------------------------------------------
// cp.async helpers (LDGSTS on sm_103a)
// ---------------------------------------------------------------------------
__device__ __forceinline__ void cp_async16(uint32_t smem_addr, const void* gptr) {
    asm volatile("cp.async.cg.shared.global [%0], [%1], 16;\n"
                 :: "r"(smem_addr), "l"(gptr) : "memory");
}
__device__ __forceinline__ void cp_commit() {
    asm volatile("cp.async.commit_group;\n" ::: "memory");
}
__device__ __forceinline__ void cp_wait_all() {
    asm volatile("cp.async.wait_group 0;\n" ::: "memory");
}

// ---------------------------------------------------------------------------
// Kernel 1: w[d] = sum_u W[d,u] * v[u].  64 blocks x 128 threads, warp-per-row.
// Triggers PDL completion immediately so k_chunk can co-start its tile-0 load.
// ---------------------------------------------------------------------------
__global__ void k_wv(const float* __restrict__ W, const float* __restrict__ v) {
    cudaTriggerProgrammaticLaunchCompletion();

    const int lane = threadIdx.x & 31;
    const int warp = threadIdx.x >> 5;
    const int r = blockIdx.x * 4 + warp;           // 64*4 = 256 rows

    const float4* v4 = (const float4*)v;
    const float4 va = v4[lane];
    const float4 vb = v4[32 + lane];

    const float4* row = (const float4*)(W + r * D_);
    const float4 xa = row[lane];
    const float4 xb = row[32 + lane];
    float s = xa.x * va.x + xa.y * va.y + xa.z * va.z + xa.w * va.w
            + xb.x * vb.x + xb.y * vb.y + xb.z * vb.z + xb.w * vb.w;
    #pragma unroll
    for (int o = 16; o > 0; o >>= 1) s += __shfl_xor_sync(0xffffffffu, s, o);
    if (lane == 0) g_w[r] = s;
}

// ---------------------------------------------------------------------------
// Kernel 2: fused scores + online softmax + weighted accumulation + merge.
// One block per (b, chunk). x is read from DRAM exactly once, via a
// double-buffered cp.async pipeline. The last-arriving block of each b
// performs the 4-way softmax merge and writes out[b,:].
// ---------------------------------------------------------------------------
__global__ __launch_bounds__(256) void k_chunk(const float* __restrict__ x,
                                               float* __restrict__ out) {
    __shared__ float sx[2][TSUB * D_];   // 2 x 32 KB tiles
    __shared__ float s_vals[TSUB];       // per-row scores
    __shared__ float p_vals[TSUB];       // per-row exp(score - m)
    __shared__ int   s_last;             // am I the last block for this b?

    const int tid  = threadIdx.x;
    const int lane = tid & 31;
    const int warp = tid >> 5;
    const int b = blockIdx.y;
    const int c = blockIdx.x;

    const size_t base = ((size_t)b * T_ + (size_t)c * TCHUNK) * D_;

    const uint32_t sb0 = (uint32_t)__cvta_generic_to_shared(&sx[0][0]);
    const uint32_t sb1 = (uint32_t)__cvta_generic_to_shared(&sx[1][0]);

    // issue tile s into buffer buf (8 x 16B per thread = 32 KB total)
    auto issue_tile = [&](int s, int buf) {
        const float4* gx = (const float4*)(x + base + (size_t)s * TSUB * D_);
        const uint32_t sb = buf ? sb1 : sb0;
        #pragma unroll
        for (int i = 0; i < 8; i++)
            cp_async16(sb + (uint32_t)(i * 256 + tid) * 16u, gx + i * 256 + tid);
        cp_commit();
    };

    // Tile 0 does not depend on w -> issue it BEFORE waiting for k_wv.
    issue_tile(0, 0);

    // Wait for k_wv's grid to complete, then pick up w fragments.
    cudaGridDependencySynchronize();
    const float4* w4 = (const float4*)g_w;
    const float4 wa = w4[lane];
    const float4 wb = w4[32 + lane];

    float m = -INFINITY;   // running max      (identical across threads)
    float Z = 0.0f;        // running sum-exp  (identical across threads)
    float acc = 0.0f;      // thread tid owns output dim d = tid

    for (int s = 0; s < NSUB; s++) {
        const int cur = s & 1;

        cp_wait_all();          // tile s landed (only one group ever in flight)
        __syncthreads();        // make it visible block-wide; also guarantees
                                // everyone is done reading buffer cur^1

        if (s + 1 < NSUB) issue_tile(s + 1, cur ^ 1);   // overlaps compute below

        // ---- warp-per-row dot: scores for 32 rows ----
        const float* tile = &sx[cur][0];
        #pragma unroll
        for (int j = 0; j < 4; j++) {
            const int row = warp * 4 + j;
            const float4* r4 = (const float4*)(tile + row * D_);
            float4 xa = r4[lane];
            float4 xb = r4[32 + lane];
            float sc = xa.x * wa.x + xa.y * wa.y + xa.z * wa.z + xa.w * wa.w
                     + xb.x * wb.x + xb.y * wb.y + xb.z * wb.z + xb.w * wb.w;
            #pragma unroll
            for (int o = 16; o > 0; o >>= 1) sc += __shfl_xor_sync(0xffffffffu, sc, o);
            if (lane == 0) s_vals[row] = sc;
        }
        __syncthreads();

        // ---- online softmax update (all threads compute identical m/scale) ----
        float msub = -INFINITY;
        #pragma unroll
        for (int t = 0; t < TSUB; t++) msub = fmaxf(msub, s_vals[t]);
        const float mnew  = fmaxf(m, msub);
        const float scale = __expf(m - mnew);   // 0 on first subtile (m = -inf)

        if (tid < TSUB) p_vals[tid] = __expf(s_vals[tid] - mnew);
        __syncthreads();

        acc *= scale;
        Z   *= scale;
        float zs = 0.0f;
        #pragma unroll
        for (int t = 0; t < TSUB; t++) {
            const float p = p_vals[t];                    // broadcast LDS
            acc = fmaf(p, tile[t * D_ + tid], acc);       // conflict-free LDS
            zs += p;
        }
        Z += zs;
        m  = mnew;
        // no trailing sync: next iteration's post-wait __syncthreads covers
        // the buffer swap, and s_vals/p_vals rewrites happen after later syncs.
    }

    // ---- publish partials ----
    const int idx = b * NCHUNK + c;
    g_pacc[(size_t)idx * D_ + tid] = acc;
    if (tid == 0) { g_pm[idx] = m; g_pz[idx] = Z; }
    __threadfence();          // each thread's partial store visible device-wide
    __syncthreads();          // whole block's stores done before the arrival

    if (tid == 0) {
        const unsigned old = atomicAdd(&g_cnt[b], 1u);
        s_last = (old == NCHUNK - 1);
    }
    __syncthreads();

    // ---- last block of this b performs the softmax merge ----
    if (s_last) {
        if (tid == 0) g_cnt[b] = 0;   // reset for the next graph replay

        float M = -INFINITY;
        #pragma unroll
        for (int k = 0; k < NCHUNK; k++) M = fmaxf(M, g_pm[b * NCHUNK + k]);

        float Zt = 0.0f, o = 0.0f;
        #pragma unroll
        for (int k = 0; k < NCHUNK; k++) {
            const float e = __expf(g_pm[b * NCHUNK + k] - M);
            Zt += e * g_pz[b * NCHUNK + k];
            o  += e * g_pacc[(size_t)(b * NCHUNK + k) * D_ + tid];
        }
        out[b * D_ + tid] = o / Zt;
    }
}

// ---------------------------------------------------------------------------
// Inputs (metadata order): 0:x 1:g 2:W 3:Wg 4:b 5:v
// g, Wg, b are provably dead (softmax shift invariance).
// ---------------------------------------------------------------------------
extern "C" void kernel_launch(void* const* d_in, const int* in_sizes, int n_in,
                              void* d_out, int out_size) {
    const float* x = (const float*)d_in[0];
    const float* W = (const float*)d_in[2];
    const float* v = (const float*)d_in[5];
    float* out = (float*)d_out;

    k_wv<<<64, 128>>>(W, v);

    // k_chunk launched with PDL so its tile-0 loads overlap k_wv.
    cudaLaunchConfig_t cfg = {};
    cfg.gridDim  = dim3(NCHUNK, B_);
    cfg.blockDim = dim3(256);
    cfg.dynamicSmemBytes = 0;
    cfg.stream = 0;
    cudaLaunchAttribute attrs[1];
    attrs[0].id = cudaLaunchAttributeProgrammaticStreamSerialization;
    attrs[0].val.programmaticStreamSerializationAllowed = 1;
    cfg.attrs = attrs;
    cfg.numAttrs = 1;
    cudaLaunchKernelEx(&cfg, k_chunk, x, out);
}

// round 6
// speedup vs baseline: 1.1283x; 1.1283x over previous
#include <cuda_runtime.h>
#include <math.h>
#include <stdint.h>

// Problem shape (fixed by the reference): B=64, T=2048, D=U=256.
#define B_     64
#define T_     2048
#define D_     256
#define NCHUNK 4                 // T-chunks per batch row
#define TCHUNK (T_ / NCHUNK)     // 512 t-rows per block
#define TSUB   32                // rows per SMEM subtile
#define NSUB   (TCHUNK / TSUB)   // 16 subtiles
#define NBUF   3                 // cp.async pipeline depth

// Scratch (allocation-free rule -> __device__ globals)
__device__ float g_w[D_];                       // w = W @ v
__device__ float g_pm[B_ * NCHUNK];             // per-chunk running max
__device__ float g_pz[B_ * NCHUNK];             // per-chunk running sum(exp)
__device__ float g_pacc[B_ * NCHUNK * D_];      // per-chunk weighted accumulators

// ---------------------------------------------------------------------------
// cp.async helpers (LDGSTS on sm_103a)
// ---------------------------------------------------------------------------
__device__ __forceinline__ void cp_async16(uint32_t smem_addr, const void* gptr) {
    asm volatile("cp.async.cg.shared.global [%0], [%1], 16;\n"
                 :: "r"(smem_addr), "l"(gptr) : "memory");
}
__device__ __forceinline__ void cp_commit() {
    asm volatile("cp.async.commit_group;\n" ::: "memory");
}
__device__ __forceinline__ void cp_wait1() {   // allow newest group in flight
    asm volatile("cp.async.wait_group 1;\n" ::: "memory");
}
__device__ __forceinline__ void cp_wait0() {   // drain everything
    asm volatile("cp.async.wait_group 0;\n" ::: "memory");
}

// ---------------------------------------------------------------------------
// Kernel 1: w[d] = sum_u W[d,u] * v[u].  64 blocks x 128 threads, warp-per-row.
// ---------------------------------------------------------------------------
__global__ void k_wv(const float* __restrict__ W, const float* __restrict__ v) {
    const int lane = threadIdx.x & 31;
    const int warp = threadIdx.x >> 5;
    const int r = blockIdx.x * 4 + warp;           // 64*4 = 256 rows

    const float4* v4 = (const float4*)v;
    const float4 va = v4[lane];
    const float4 vb = v4[32 + lane];

    const float4* row = (const float4*)(W + r * D_);
    const float4 xa = row[lane];
    const float4 xb = row[32 + lane];
    float s = xa.x * va.x + xa.y * va.y + xa.z * va.z + xa.w * va.w
            + xb.x * vb.x + xb.y * vb.y + xb.z * vb.z + xb.w * vb.w;
    #pragma unroll
    for (int o = 16; o > 0; o >>= 1) s += __shfl_xor_sync(0xffffffffu, s, o);
    if (lane == 0) g_w[r] = s;
}

// ---------------------------------------------------------------------------
// Kernel 2: fused scores + online softmax + weighted accumulation.
// One block per (b, chunk). x is read from DRAM exactly once, via a
// 3-stage cp.async pipeline (tiles s+1 and s+2 stream under tile s compute).
// ---------------------------------------------------------------------------
__global__ __launch_bounds__(256) void k_chunk(const float* __restrict__ x) {
    __shared__ float sx[NBUF][TSUB * D_];   // 3 x 32 KB tiles
    __shared__ float s_vals[TSUB];          // per-row scores
    __shared__ float p_vals[TSUB];          // per-row exp(score - m)

    const int tid  = threadIdx.x;
    const int lane = tid & 31;
    const int warp = tid >> 5;
    const int b = blockIdx.y;
    const int c = blockIdx.x;

    // w fragments held in registers (same two float4 per lane for every row)
    const float4* w4 = (const float4*)g_w;
    const float4 wa = w4[lane];
    const float4 wb = w4[32 + lane];

    float m = -INFINITY;   // running max      (identical across threads)
    float Z = 0.0f;        // running sum-exp  (identical across threads)
    float acc = 0.0f;      // thread tid owns output dim d = tid

    const size_t base = ((size_t)b * T_ + (size_t)c * TCHUNK) * D_;

    uint32_t sb[NBUF];
    #pragma unroll
    for (int i = 0; i < NBUF; i++)
        sb[i] = (uint32_t)__cvta_generic_to_shared(&sx[i][0]);

    // issue tile s into buffer buf (8 x 16B per thread = 32 KB total)
    auto issue_tile = [&](int s, int buf) {
        const float4* gx = (const float4*)(x + base + (size_t)s * TSUB * D_);
        #pragma unroll
        for (int i = 0; i < 8; i++)
            cp_async16(sb[buf] + (uint32_t)(i * 256 + tid) * 16u, gx + i * 256 + tid);
        cp_commit();
    };

    issue_tile(0, 0);
    issue_tile(1, 1);

    for (int s = 0; s < NSUB; s++) {
        const int cur = s % NBUF;

        // tile s must be resident; tile s+1 (if issued) may stay in flight
        if (s + 1 < NSUB) cp_wait1(); else cp_wait0();
        __syncthreads();        // tile s visible block-wide; also guarantees
                                // everyone finished reading buffer (s-1)%NBUF

        if (s + 2 < NSUB) issue_tile(s + 2, (s + 2) % NBUF);  // overlaps compute

        // ---- warp-per-row dot: scores for 32 rows ----
        const float* tile = &sx[cur][0];
        #pragma unroll
        for (int j = 0; j < 4; j++) {
            const int row = warp * 4 + j;
            const float4* r4 = (const float4*)(tile + row * D_);
            float4 xa = r4[lane];
            float4 xb = r4[32 + lane];
            float sc = xa.x * wa.x + xa.y * wa.y + xa.z * wa.z + xa.w * wa.w
                     + xb.x * wb.x + xb.y * wb.y + xb.z * wb.z + xb.w * wb.w;
            #pragma unroll
            for (int o = 16; o > 0; o >>= 1) sc += __shfl_xor_sync(0xffffffffu, sc, o);
            if (lane == 0) s_vals[row] = sc;
        }
        __syncthreads();

        // ---- online softmax update (all threads compute identical m/scale) ----
        float msub = -INFINITY;
        #pragma unroll
        for (int t = 0; t < TSUB; t++) msub = fmaxf(msub, s_vals[t]);
        const float mnew  = fmaxf(m, msub);
        const float scale = __expf(m - mnew);   // 0 on first subtile (m = -inf)

        if (tid < TSUB) p_vals[tid] = __expf(s_vals[tid] - mnew);
        __syncthreads();

        acc *= scale;
        Z   *= scale;
        float zs = 0.0f;
        #pragma unroll
        for (int t = 0; t < TSUB; t++) {
            const float p = p_vals[t];                    // broadcast LDS
            acc = fmaf(p, tile[t * D_ + tid], acc);       // conflict-free LDS
            zs += p;
        }
        Z += zs;
        m  = mnew;
        // no trailing sync: buffer cur is reused NBUF=3 tiles later, and the
        // next iteration's post-wait __syncthreads orders all reads before
        // any re-fill; s_vals/p_vals rewrites happen after later syncs.
    }

    const int idx = b * NCHUNK + c;
    g_pacc[(size_t)idx * D_ + tid] = acc;
    if (tid == 0) { g_pm[idx] = m; g_pz[idx] = Z; }
}

// ---------------------------------------------------------------------------
// Kernel 3: merge the NCHUNK chunk partials per batch row, write out[b, d].
// ---------------------------------------------------------------------------
__global__ void k_merge(float* __restrict__ out) {
    const int b = blockIdx.x;
    const int tid = threadIdx.x;

    float M = -INFINITY;
    #pragma unroll
    for (int c = 0; c < NCHUNK; c++) M = fmaxf(M, g_pm[b * NCHUNK + c]);

    float Z = 0.0f, o = 0.0f;
    #pragma unroll
    for (int c = 0; c < NCHUNK; c++) {
        const float e = __expf(g_pm[b * NCHUNK + c] - M);
        Z += e * g_pz[b * NCHUNK + c];
        o += e * g_pacc[(size_t)(b * NCHUNK + c) * D_ + tid];
    }
    out[b * D_ + tid] = o / Z;
}

// ---------------------------------------------------------------------------
// Inputs (metadata order): 0:x 1:g 2:W 3:Wg 4:b 5:v
// g, Wg, b are provably dead (softmax shift invariance).
// ---------------------------------------------------------------------------
extern "C" void kernel_launch(void* const* d_in, const int* in_sizes, int n_in,
                              void* d_out, int out_size) {
    const float* x = (const float*)d_in[0];
    const float* W = (const float*)d_in[2];
    const float* v = (const float*)d_in[5];
    float* out = (float*)d_out;

    k_wv<<<64, 128>>>(W, v);
    k_chunk<<<dim3(NCHUNK, B_), 256>>>(x);
    k_merge<<<B_, 256>>>(out);
}

// round 7
// speedup vs baseline: 1.2510x; 1.1087x over previous
#include <cuda_runtime.h>
#include <math.h>
#include <stdint.h>

// Problem shape (fixed by the reference): B=64, T=2048, D=U=256.
#define B_     64
#define T_     2048
#define D_     256
#define NCHUNK 8                 // T-chunks per batch row -> grid 512, one wave
#define TCHUNK (T_ / NCHUNK)     // 256 t-rows per block
#define TSUB   16                // rows per SMEM subtile (16 KB)
#define NSUB   (TCHUNK / TSUB)   // 16 subtiles

// Scratch (allocation-free rule -> __device__ globals)
__device__ float g_w[D_];                       // w = W @ v
__device__ float g_pm[B_ * NCHUNK];             // per-chunk running max
__device__ float g_pz[B_ * NCHUNK];             // per-chunk running sum(exp)
__device__ float g_pacc[B_ * NCHUNK * D_];      // per-chunk weighted accumulators

// ---------------------------------------------------------------------------
// cp.async helpers (LDGSTS on sm_103a)
// ---------------------------------------------------------------------------
__device__ __forceinline__ void cp_async16(uint32_t smem_addr, const void* gptr) {
    asm volatile("cp.async.cg.shared.global [%0], [%1], 16;\n"
                 :: "r"(smem_addr), "l"(gptr) : "memory");
}
__device__ __forceinline__ void cp_commit() {
    asm volatile("cp.async.commit_group;\n" ::: "memory");
}
__device__ __forceinline__ void cp_wait0() {
    asm volatile("cp.async.wait_group 0;\n" ::: "memory");
}

// ---------------------------------------------------------------------------
// Kernel 1: w[d] = sum_u W[d,u] * v[u].  64 blocks x 128 threads, warp-per-row.
// ---------------------------------------------------------------------------
__global__ void k_wv(const float* __restrict__ W, const float* __restrict__ v) {
    const int lane = threadIdx.x & 31;
    const int warp = threadIdx.x >> 5;
    const int r = blockIdx.x * 4 + warp;           // 64*4 = 256 rows

    const float4* v4 = (const float4*)v;
    const float4 va = v4[lane];
    const float4 vb = v4[32 + lane];

    const float4* row = (const float4*)(W + r * D_);
    const float4 xa = row[lane];
    const float4 xb = row[32 + lane];
    float s = xa.x * va.x + xa.y * va.y + xa.z * va.z + xa.w * va.w
            + xb.x * vb.x + xb.y * vb.y + xb.z * vb.z + xb.w * vb.w;
    #pragma unroll
    for (int o = 16; o > 0; o >>= 1) s += __shfl_xor_sync(0xffffffffu, s, o);
    if (lane == 0) g_w[r] = s;
}

// ---------------------------------------------------------------------------
// Kernel 2: fused scores + online softmax + register-resident accumulation.
// One block per (b, chunk); 512 blocks = one full wave at 4 blocks/SM.
// Each warp owns 2 rows per subtile: x-fragments loaded once from SMEM for the
// dot stay in registers and feed the p-weighted accumulation (no 2nd SMEM pass).
// ---------------------------------------------------------------------------
__global__ __launch_bounds__(256, 4) void k_chunk(const float* __restrict__ x) {
    __shared__ float sx[2][TSUB * D_];   // 2 x 16 KB tiles (reused as reduce buf)
    __shared__ float s_vals[TSUB];       // per-row scores
    __shared__ float p_vals[TSUB];       // per-row exp(score - m)

    const int tid  = threadIdx.x;
    const int lane = tid & 31;
    const int warp = tid >> 5;
    const int b = blockIdx.y;
    const int c = blockIdx.x;

    // w fragments (same two float4 per lane for every row)
    const float4* w4 = (const float4*)g_w;
    const float4 wa = w4[lane];
    const float4 wb = w4[32 + lane];

    float m = -INFINITY;   // running max      (identical across threads)
    float Z = 0.0f;        // running sum-exp  (identical across threads)
    // per-warp partial output: lane holds dims {4*lane+k} and {128+4*lane+k}
    float accA[4] = {0.f, 0.f, 0.f, 0.f};
    float accB[4] = {0.f, 0.f, 0.f, 0.f};

    const size_t base = ((size_t)b * T_ + (size_t)c * TCHUNK) * D_;

    const uint32_t sb0 = (uint32_t)__cvta_generic_to_shared(&sx[0][0]);
    const uint32_t sb1 = (uint32_t)__cvta_generic_to_shared(&sx[1][0]);

    // issue tile s into buffer buf (4 x 16B per thread = 16 KB total)
    auto issue_tile = [&](int s, int buf) {
        const float4* gx = (const float4*)(x + base + (size_t)s * TSUB * D_);
        const uint32_t sb = buf ? sb1 : sb0;
        #pragma unroll
        for (int i = 0; i < 4; i++)
            cp_async16(sb + (uint32_t)(i * 256 + tid) * 16u, gx + i * 256 + tid);
        cp_commit();
    };

    issue_tile(0, 0);

    const int r0 = warp * 2;       // this warp's two rows in every subtile
    const int r1 = warp * 2 + 1;

    for (int s = 0; s < NSUB; s++) {
        const int cur = s & 1;

        cp_wait0();             // tile s landed (one group in flight max)
        __syncthreads();        // visible block-wide; buffer cur^1 free

        if (s + 1 < NSUB) issue_tile(s + 1, cur ^ 1);   // overlaps compute

        // ---- load this warp's 2 rows into registers + dot ----
        const float* tile = &sx[cur][0];
        const float4* q0 = (const float4*)(tile + r0 * D_);
        const float4* q1 = (const float4*)(tile + r1 * D_);
        const float4 xa0 = q0[lane],      xb0 = q0[32 + lane];
        const float4 xa1 = q1[lane],      xb1 = q1[32 + lane];

        float sc0 = xa0.x * wa.x + xa0.y * wa.y + xa0.z * wa.z + xa0.w * wa.w
                  + xb0.x * wb.x + xb0.y * wb.y + xb0.z * wb.z + xb0.w * wb.w;
        float sc1 = xa1.x * wa.x + xa1.y * wa.y + xa1.z * wa.z + xa1.w * wa.w
                  + xb1.x * wb.x + xb1.y * wb.y + xb1.z * wb.z + xb1.w * wb.w;
        #pragma unroll
        for (int o = 16; o > 0; o >>= 1) {
            sc0 += __shfl_xor_sync(0xffffffffu, sc0, o);
            sc1 += __shfl_xor_sync(0xffffffffu, sc1, o);
        }
        if (lane == 0) { s_vals[r0] = sc0; s_vals[r1] = sc1; }
        __syncthreads();

        // ---- online softmax update (identical across threads) ----
        float msub = -INFINITY;
        #pragma unroll
        for (int t = 0; t < TSUB; t++) msub = fmaxf(msub, s_vals[t]);
        const float mnew  = fmaxf(m, msub);
        const float scale = __expf(m - mnew);   // 0 on first subtile

        if (tid < TSUB) p_vals[tid] = __expf(s_vals[tid] - mnew);
        __syncthreads();

        Z *= scale;
        float zs = 0.0f;
        #pragma unroll
        for (int t = 0; t < TSUB; t++) zs += p_vals[t];   // broadcast LDS
        Z += zs;

        const float p0 = p_vals[r0];
        const float p1 = p_vals[r1];
        #pragma unroll
        for (int k = 0; k < 4; k++) { accA[k] *= scale; accB[k] *= scale; }
        accA[0] = fmaf(p0, xa0.x, accA[0]);  accA[1] = fmaf(p0, xa0.y, accA[1]);
        accA[2] = fmaf(p0, xa0.z, accA[2]);  accA[3] = fmaf(p0, xa0.w, accA[3]);
        accB[0] = fmaf(p0, xb0.x, accB[0]);  accB[1] = fmaf(p0, xb0.y, accB[1]);
        accB[2] = fmaf(p0, xb0.z, accB[2]);  accB[3] = fmaf(p0, xb0.w, accB[3]);
        accA[0] = fmaf(p1, xa1.x, accA[0]);  accA[1] = fmaf(p1, xa1.y, accA[1]);
        accA[2] = fmaf(p1, xa1.z, accA[2]);  accA[3] = fmaf(p1, xa1.w, accA[3]);
        accB[0] = fmaf(p1, xb1.x, accB[0]);  accB[1] = fmaf(p1, xb1.y, accB[1]);
        accB[2] = fmaf(p1, xb1.z, accB[2]);  accB[3] = fmaf(p1, xb1.w, accB[3]);
        m = mnew;
        // no trailing sync: next iteration's post-wait __syncthreads orders
        // all reads of buffer cur before its re-fill.
    }

    // ---- cross-warp reduction of the 8 partial output vectors ----
    // Reuse sx[0] (16 KB >= 8 warps x 1 KB). All warps are past the last
    // tile's sync; last tile lived in sx[1], so sx[0] is free to overwrite.
    float* sacc = &sx[0][0];
    ((float4*)(sacc + warp * D_))[lane]      = make_float4(accA[0], accA[1], accA[2], accA[3]);
    ((float4*)(sacc + warp * D_ + 128))[lane] = make_float4(accB[0], accB[1], accB[2], accB[3]);
    __syncthreads();

    float o = 0.0f;
    #pragma unroll
    for (int w = 0; w < 8; w++) o += sacc[w * D_ + tid];

    const int idx = b * NCHUNK + c;
    g_pacc[(size_t)idx * D_ + tid] = o;
    if (tid == 0) { g_pm[idx] = m; g_pz[idx] = Z; }
}

// ---------------------------------------------------------------------------
// Kernel 3: merge the NCHUNK chunk partials per batch row, write out[b, d].
// ---------------------------------------------------------------------------
__global__ void k_merge(float* __restrict__ out) {
    const int b = blockIdx.x;
    const int tid = threadIdx.x;

    float M = -INFINITY;
    #pragma unroll
    for (int c = 0; c < NCHUNK; c++) M = fmaxf(M, g_pm[b * NCHUNK + c]);

    float Z = 0.0f, o = 0.0f;
    #pragma unroll
    for (int c = 0; c < NCHUNK; c++) {
        const float e = __expf(g_pm[b * NCHUNK + c] - M);
        Z += e * g_pz[b * NCHUNK + c];
        o += e * g_pacc[(size_t)(b * NCHUNK + c) * D_ + tid];
    }
    out[b * D_ + tid] = o / Z;
}

// ---------------------------------------------------------------------------
// Inputs (metadata order): 0:x 1:g 2:W 3:Wg 4:b 5:v
// g, Wg, b are provably dead (softmax shift invariance).
// ---------------------------------------------------------------------------
extern "C" void kernel_launch(void* const* d_in, const int* in_sizes, int n_in,
                              void* d_out, int out_size) {
    const float* x = (const float*)d_in[0];
    const float* W = (const float*)d_in[2];
    const float* v = (const float*)d_in[5];
    float* out = (float*)d_out;

    k_wv<<<64, 128>>>(W, v);
    k_chunk<<<dim3(NCHUNK, B_), 256>>>(x);
    k_merge<<<B_, 256>>>(out);
}

// round 8
// speedup vs baseline: 1.3498x; 1.0789x over previous
#include <cuda_runtime.h>
#include <math.h>
#include <stdint.h>

// Problem shape (fixed by the reference): B=64, T=2048, D=U=256.
#define B_     64
#define T_     2048
#define D_     256
#define NCHUNK 8                 // T-chunks per batch row -> grid 512, one wave
#define TCHUNK (T_ / NCHUNK)     // 256 t-rows per block
#define TSUB   16                // rows per SMEM subtile (16 KB)
#define NSUB   (TCHUNK / TSUB)   // 16 subtiles

// Scratch (allocation-free rule -> __device__ globals)
__device__ float g_w[D_];                       // w = W @ v
__device__ float g_pm[B_ * NCHUNK];             // per-chunk running max
__device__ float g_pz[B_ * NCHUNK];             // per-chunk running sum(exp)
__device__ float g_pacc[B_ * NCHUNK * D_];      // per-chunk weighted accumulators

// ---------------------------------------------------------------------------
// cp.async helpers (LDGSTS on sm_103a)
// ---------------------------------------------------------------------------
__device__ __forceinline__ void cp_async16(uint32_t smem_addr, const void* gptr) {
    asm volatile("cp.async.cg.shared.global [%0], [%1], 16;\n"
                 :: "r"(smem_addr), "l"(gptr) : "memory");
}
__device__ __forceinline__ void cp_commit() {
    asm volatile("cp.async.commit_group;\n" ::: "memory");
}
__device__ __forceinline__ void cp_wait0() {
    asm volatile("cp.async.wait_group 0;\n" ::: "memory");
}

// ---------------------------------------------------------------------------
// Kernel 1: w[d] = sum_u W[d,u] * v[u].  64 blocks x 128 threads, warp-per-row.
// Fires PDL completion at entry so k_chunk's tile-0 loads co-start.
// ---------------------------------------------------------------------------
__global__ void k_wv(const float* __restrict__ W, const float* __restrict__ v) {
    cudaTriggerProgrammaticLaunchCompletion();

    const int lane = threadIdx.x & 31;
    const int warp = threadIdx.x >> 5;
    const int r = blockIdx.x * 4 + warp;           // 64*4 = 256 rows

    const float4* v4 = (const float4*)v;
    const float4 va = v4[lane];
    const float4 vb = v4[32 + lane];

    const float4* row = (const float4*)(W + r * D_);
    const float4 xa = row[lane];
    const float4 xb = row[32 + lane];
    float s = xa.x * va.x + xa.y * va.y + xa.z * va.z + xa.w * va.w
            + xb.x * vb.x + xb.y * vb.y + xb.z * vb.z + xb.w * vb.w;
    #pragma unroll
    for (int o = 16; o > 0; o >>= 1) s += __shfl_xor_sync(0xffffffffu, s, o);
    if (lane == 0) g_w[r] = s;
}

// ---------------------------------------------------------------------------
// Kernel 2: fused scores + online softmax + register-resident accumulation.
// One block per (b, chunk); 512 blocks = one full wave at 4 blocks/SM.
// Tile-0 cp.async is issued BEFORE the PDL grid-dependency wait on k_wv.
// Per tile: 2 barriers only; per-warp Z tracked in registers (no p broadcast).
// ---------------------------------------------------------------------------
__global__ __launch_bounds__(256, 4) void k_chunk(const float* __restrict__ x) {
    __shared__ float sx[2][TSUB * D_];   // 2 x 16 KB tiles (reused as reduce buf)
    __shared__ float s_vals[TSUB];       // per-row scores (also end Z-reduce buf)

    const int tid  = threadIdx.x;
    const int lane = tid & 31;
    const int warp = tid >> 5;
    const int b = blockIdx.y;
    const int c = blockIdx.x;

    const size_t base = ((size_t)b * T_ + (size_t)c * TCHUNK) * D_;

    const uint32_t sb0 = (uint32_t)__cvta_generic_to_shared(&sx[0][0]);
    const uint32_t sb1 = (uint32_t)__cvta_generic_to_shared(&sx[1][0]);

    // issue tile s into buffer buf (4 x 16B per thread = 16 KB total)
    auto issue_tile = [&](int s, int buf) {
        const float4* gx = (const float4*)(x + base + (size_t)s * TSUB * D_);
        const uint32_t sb = buf ? sb1 : sb0;
        #pragma unroll
        for (int i = 0; i < 4; i++)
            cp_async16(sb + (uint32_t)(i * 256 + tid) * 16u, gx + i * 256 + tid);
        cp_commit();
    };

    // Tile 0 does not depend on w -> issue before waiting for k_wv.
    issue_tile(0, 0);

    cudaGridDependencySynchronize();           // k_wv done; g_w valid
    const float4* w4 = (const float4*)g_w;
    const float4 wa = w4[lane];
    const float4 wb = w4[32 + lane];

    float m  = -INFINITY;  // running max (identical across threads)
    float Zw = 0.0f;       // THIS WARP's partial sum-exp (rows r0,r1 per tile)
    // per-warp partial output: lane holds dims {4*lane+k} and {128+4*lane+k}
    float accA[4] = {0.f, 0.f, 0.f, 0.f};
    float accB[4] = {0.f, 0.f, 0.f, 0.f};

    const int r0 = warp * 2;       // this warp's two rows in every subtile
    const int r1 = warp * 2 + 1;

    for (int s = 0; s < NSUB; s++) {
        const int cur = s & 1;

        cp_wait0();             // tile s landed (one group in flight max)
        __syncthreads();        // visible block-wide; buffer cur^1 free;
                                // also orders prev-iter s_vals reads before
                                // this iter's s_vals writes

        if (s + 1 < NSUB) issue_tile(s + 1, cur ^ 1);   // overlaps compute

        // ---- load this warp's 2 rows into registers + dot ----
        const float* tile = &sx[cur][0];
        const float4* q0 = (const float4*)(tile + r0 * D_);
        const float4* q1 = (const float4*)(tile + r1 * D_);
        const float4 xa0 = q0[lane],      xb0 = q0[32 + lane];
        const float4 xa1 = q1[lane],      xb1 = q1[32 + lane];

        float sc0 = xa0.x * wa.x + xa0.y * wa.y + xa0.z * wa.z + xa0.w * wa.w
                  + xb0.x * wb.x + xb0.y * wb.y + xb0.z * wb.z + xb0.w * wb.w;
        float sc1 = xa1.x * wa.x + xa1.y * wa.y + xa1.z * wa.z + xa1.w * wa.w
                  + xb1.x * wb.x + xb1.y * wb.y + xb1.z * wb.z + xb1.w * wb.w;
        #pragma unroll
        for (int o = 16; o > 0; o >>= 1) {
            sc0 += __shfl_xor_sync(0xffffffffu, sc0, o);
            sc1 += __shfl_xor_sync(0xffffffffu, sc1, o);
        }
        if (lane == 0) { s_vals[r0] = sc0; s_vals[r1] = sc1; }
        __syncthreads();

        // ---- online softmax update (identical mnew across threads) ----
        float msub = -INFINITY;
        #pragma unroll
        for (int t = 0; t < TSUB; t++) msub = fmaxf(msub, s_vals[t]);
        const float mnew  = fmaxf(m, msub);
        const float scale = __expf(m - mnew);   // 0 on first subtile

        // this warp's p's computed locally (sc0/sc1 live in all lanes)
        const float p0 = __expf(sc0 - mnew);
        const float p1 = __expf(sc1 - mnew);
        Zw = Zw * scale + p0 + p1;

        #pragma unroll
        for (int k = 0; k < 4; k++) { accA[k] *= scale; accB[k] *= scale; }
        accA[0] = fmaf(p0, xa0.x, accA[0]);  accA[1] = fmaf(p0, xa0.y, accA[1]);
        accA[2] = fmaf(p0, xa0.z, accA[2]);  accA[3] = fmaf(p0, xa0.w, accA[3]);
        accB[0] = fmaf(p0, xb0.x, accB[0]);  accB[1] = fmaf(p0, xb0.y, accB[1]);
        accB[2] = fmaf(p0, xb0.z, accB[2]);  accB[3] = fmaf(p0, xb0.w, accB[3]);
        accA[0] = fmaf(p1, xa1.x, accA[0]);  accA[1] = fmaf(p1, xa1.y, accA[1]);
        accA[2] = fmaf(p1, xa1.z, accA[2]);  accA[3] = fmaf(p1, xa1.w, accA[3]);
        accB[0] = fmaf(p1, xb1.x, accB[0]);  accB[1] = fmaf(p1, xb1.y, accB[1]);
        accB[2] = fmaf(p1, xb1.z, accB[2]);  accB[3] = fmaf(p1, xb1.w, accB[3]);
        m = mnew;
    }

    // ---- cross-warp reduction: 8 partial output vectors + 8 partial Z ----
    __syncthreads();   // all warps done reading s_vals / last tile
    float* sacc = &sx[0][0];
    ((float4*)(sacc + warp * D_))[lane]       = make_float4(accA[0], accA[1], accA[2], accA[3]);
    ((float4*)(sacc + warp * D_ + 128))[lane] = make_float4(accB[0], accB[1], accB[2], accB[3]);
    if (lane == 0) s_vals[warp] = Zw;
    __syncthreads();

    float o = 0.0f;
    #pragma unroll
    for (int w = 0; w < 8; w++) o += sacc[w * D_ + tid];

    const int idx = b * NCHUNK + c;
    g_pacc[(size_t)idx * D_ + tid] = o;
    if (tid == 0) {
        float Z = 0.0f;
        #pragma unroll
        for (int w = 0; w < 8; w++) Z += s_vals[w];
        g_pm[idx] = m; g_pz[idx] = Z;
    }
}

// ---------------------------------------------------------------------------
// Kernel 3: merge the NCHUNK chunk partials per batch row, write out[b, d].
// PDL: launches early, waits for k_chunk's grid in-kernel.
// ---------------------------------------------------------------------------
__global__ void k_merge(float* __restrict__ out) {
    cudaGridDependencySynchronize();

    const int b = blockIdx.x;
    const int tid = threadIdx.x;

    float M = -INFINITY;
    #pragma unroll
    for (int c = 0; c < NCHUNK; c++) M = fmaxf(M, g_pm[b * NCHUNK + c]);

    float Z = 0.0f, o = 0.0f;
    #pragma unroll
    for (int c = 0; c < NCHUNK; c++) {
        const float e = __expf(g_pm[b * NCHUNK + c] - M);
        Z += e * g_pz[b * NCHUNK + c];
        o += e * g_pacc[(size_t)(b * NCHUNK + c) * D_ + tid];
    }
    out[b * D_ + tid] = o / Z;
}

// ---------------------------------------------------------------------------
// Inputs (metadata order): 0:x 1:g 2:W 3:Wg 4:b 5:v
// g, Wg, b are provably dead (softmax shift invariance).
// ---------------------------------------------------------------------------
extern "C" void kernel_launch(void* const* d_in, const int* in_sizes, int n_in,
                              void* d_out, int out_size) {
    const float* x = (const float*)d_in[0];
    const float* W = (const float*)d_in[2];
    const float* v = (const float*)d_in[5];
    float* out = (float*)d_out;

    k_wv<<<64, 128>>>(W, v);

    cudaLaunchAttribute pdl[1];
    pdl[0].id = cudaLaunchAttributeProgrammaticStreamSerialization;
    pdl[0].val.programmaticStreamSerializationAllowed = 1;

    cudaLaunchConfig_t cfg1 = {};
    cfg1.gridDim  = dim3(NCHUNK, B_);
    cfg1.blockDim = dim3(256);
    cfg1.stream = 0;
    cfg1.attrs = pdl;
    cfg1.numAttrs = 1;
    cudaLaunchKernelEx(&cfg1, k_chunk, x);

    cudaLaunchConfig_t cfg2 = {};
    cfg2.gridDim  = dim3(B_);
    cfg2.blockDim = dim3(256);
    cfg2.stream = 0;
    cfg2.attrs = pdl;
    cfg2.numAttrs = 1;
    cudaLaunchKernelEx(&cfg2, k_merge, out);
}

// round 9
// speedup vs baseline: 1.3513x; 1.0011x over previous
#include <cuda_runtime.h>
#include <math.h>
#include <stdint.h>

// Problem shape (fixed by the reference): B=64, T=2048, D=U=256.
#define B_     64
#define T_     2048
#define D_     256
#define NCHUNK 8                 // T-chunks per batch row -> grid 512, one wave
#define TCHUNK (T_ / NCHUNK)     // 256 t-rows per block
#define TSUB   16                // rows per SMEM subtile (16 KB)
#define NSUB   (TCHUNK / TSUB)   // 16 subtiles
#define NBUF   3                 // cp.async pipeline depth (2 groups in flight)

// Scratch (allocation-free rule -> __device__ globals)
__device__ float g_w[D_];                       // w = W @ v
__device__ float g_pm[B_ * NCHUNK];             // per-chunk max
__device__ float g_pz[B_ * NCHUNK];             // per-chunk sum(exp)
__device__ float g_pacc[B_ * NCHUNK * D_];      // per-chunk weighted accumulators

// ---------------------------------------------------------------------------
// cp.async helpers (LDGSTS on sm_103a)
// ---------------------------------------------------------------------------
__device__ __forceinline__ void cp_async16(uint32_t smem_addr, const void* gptr) {
    asm volatile("cp.async.cg.shared.global [%0], [%1], 16;\n"
                 :: "r"(smem_addr), "l"(gptr) : "memory");
}
__device__ __forceinline__ void cp_commit() {
    asm volatile("cp.async.commit_group;\n" ::: "memory");
}
__device__ __forceinline__ void cp_wait1() {   // newest group may stay in flight
    asm volatile("cp.async.wait_group 1;\n" ::: "memory");
}
__device__ __forceinline__ void cp_wait0() {   // drain everything
    asm volatile("cp.async.wait_group 0;\n" ::: "memory");
}

// ---------------------------------------------------------------------------
// Kernel 1: w[d] = sum_u W[d,u] * v[u].  64 blocks x 128 threads, warp-per-row.
// Fires PDL completion at entry so k_chunk's tile-0 loads co-start.
// ---------------------------------------------------------------------------
__global__ void k_wv(const float* __restrict__ W, const float* __restrict__ v) {
    cudaTriggerProgrammaticLaunchCompletion();

    const int lane = threadIdx.x & 31;
    const int warp = threadIdx.x >> 5;
    const int r = blockIdx.x * 4 + warp;           // 64*4 = 256 rows

    const float4* v4 = (const float4*)v;
    const float4 va = v4[lane];
    const float4 vb = v4[32 + lane];

    const float4* row = (const float4*)(W + r * D_);
    const float4 xa = row[lane];
    const float4 xb = row[32 + lane];
    float s = xa.x * va.x + xa.y * va.y + xa.z * va.z + xa.w * va.w
            + xb.x * vb.x + xb.y * vb.y + xb.z * vb.z + xb.w * vb.w;
    #pragma unroll
    for (int o = 16; o > 0; o >>= 1) s += __shfl_xor_sync(0xffffffffu, s, o);
    if (lane == 0) g_w[r] = s;
}

// ---------------------------------------------------------------------------
// Kernel 2: fused scores + PER-WARP online softmax + register accumulation.
// One block per (b, chunk); 512 blocks = one full wave at 4 blocks/SM.
// Each warp runs an independent online-softmax over its 2 rows per subtile
// (no cross-warp coupling in the mainloop -> ONE barrier per tile). The 8
// warp-states merge associatively at kernel end.
// 3-stage cp.async pipeline keeps 2 tiles (32 KB/block) in DRAM flight.
// ---------------------------------------------------------------------------
__global__ __launch_bounds__(256, 4) void k_chunk(const float* __restrict__ x) {
    __shared__ float sx[NBUF][TSUB * D_];   // 3 x 16 KB tiles (buf0 reused at end)
    __shared__ float s_m[8];                // per-warp max (end merge)
    __shared__ float s_z[8];                // per-warp Z   (end merge)

    const int tid  = threadIdx.x;
    const int lane = tid & 31;
    const int warp = tid >> 5;
    const int b = blockIdx.y;
    const int c = blockIdx.x;

    const size_t base = ((size_t)b * T_ + (size_t)c * TCHUNK) * D_;

    uint32_t sb[NBUF];
    #pragma unroll
    for (int i = 0; i < NBUF; i++)
        sb[i] = (uint32_t)__cvta_generic_to_shared(&sx[i][0]);

    // issue tile s into buffer buf (4 x 16B per thread = 16 KB total)
    auto issue_tile = [&](int s, int buf) {
        const float4* gx = (const float4*)(x + base + (size_t)s * TSUB * D_);
        #pragma unroll
        for (int i = 0; i < 4; i++)
            cp_async16(sb[buf] + (uint32_t)(i * 256 + tid) * 16u, gx + i * 256 + tid);
        cp_commit();
    };

    // Tiles 0,1 do not depend on w -> issue before waiting for k_wv.
    issue_tile(0, 0);
    issue_tile(1, 1);

    cudaGridDependencySynchronize();           // k_wv done; g_w valid
    const float4* w4 = (const float4*)g_w;
    const float4 wa = w4[lane];
    const float4 wb = w4[32 + lane];

    float mw = -INFINITY;  // this warp's running max
    float Zw = 0.0f;       // this warp's running sum-exp
    // per-warp partial output: lane holds dims {4*lane+k} and {128+4*lane+k}
    float accA[4] = {0.f, 0.f, 0.f, 0.f};
    float accB[4] = {0.f, 0.f, 0.f, 0.f};

    const int r0 = warp * 2;       // this warp's two rows in every subtile
    const int r1 = warp * 2 + 1;

    for (int s = 0; s < NSUB; s++) {
        const int cur = s % NBUF;

        if (s + 1 < NSUB) cp_wait1(); else cp_wait0();   // tile s resident
        __syncthreads();        // publish tile s block-wide; buffer (s-1)%NBUF
                                // fully consumed by everyone

        if (s + 2 < NSUB) issue_tile(s + 2, (s + 2) % NBUF);  // overlaps compute

        // ---- load this warp's 2 rows into registers + dot ----
        const float* tile = &sx[cur][0];
        const float4* q0 = (const float4*)(tile + r0 * D_);
        const float4* q1 = (const float4*)(tile + r1 * D_);
        const float4 xa0 = q0[lane],      xb0 = q0[32 + lane];
        const float4 xa1 = q1[lane],      xb1 = q1[32 + lane];

        float sc0 = xa0.x * wa.x + xa0.y * wa.y + xa0.z * wa.z + xa0.w * wa.w
                  + xb0.x * wb.x + xb0.y * wb.y + xb0.z * wb.z + xb0.w * wb.w;
        float sc1 = xa1.x * wa.x + xa1.y * wa.y + xa1.z * wa.z + xa1.w * wa.w
                  + xb1.x * wb.x + xb1.y * wb.y + xb1.z * wb.z + xb1.w * wb.w;
        #pragma unroll
        for (int o = 16; o > 0; o >>= 1) {
            sc0 += __shfl_xor_sync(0xffffffffu, sc0, o);
            sc1 += __shfl_xor_sync(0xffffffffu, sc1, o);
        }

        // ---- per-warp online softmax update (no barriers, no smem) ----
        const float mnew  = fmaxf(mw, fmaxf(sc0, sc1));
        const float scale = __expf(mw - mnew);   // 0 on first subtile
        const float p0 = __expf(sc0 - mnew);
        const float p1 = __expf(sc1 - mnew);
        Zw = Zw * scale + p0 + p1;

        #pragma unroll
        for (int k = 0; k < 4; k++) { accA[k] *= scale; accB[k] *= scale; }
        accA[0] = fmaf(p0, xa0.x, accA[0]);  accA[1] = fmaf(p0, xa0.y, accA[1]);
        accA[2] = fmaf(p0, xa0.z, accA[2]);  accA[3] = fmaf(p0, xa0.w, accA[3]);
        accB[0] = fmaf(p0, xb0.x, accB[0]);  accB[1] = fmaf(p0, xb0.y, accB[1]);
        accB[2] = fmaf(p0, xb0.z, accB[2]);  accB[3] = fmaf(p0, xb0.w, accB[3]);
        accA[0] = fmaf(p1, xa1.x, accA[0]);  accA[1] = fmaf(p1, xa1.y, accA[1]);
        accA[2] = fmaf(p1, xa1.z, accA[2]);  accA[3] = fmaf(p1, xa1.w, accA[3]);
        accB[0] = fmaf(p1, xb1.x, accB[0]);  accB[1] = fmaf(p1, xb1.y, accB[1]);
        accB[2] = fmaf(p1, xb1.z, accB[2]);  accB[3] = fmaf(p1, xb1.w, accB[3]);
        mw = mnew;
    }

    // ---- merge the 8 independent warp softmax states ----
    if (lane == 0) { s_m[warp] = mw; s_z[warp] = Zw; }
    __syncthreads();            // also: everyone past last tile reads

    float M = -INFINITY;
    #pragma unroll
    for (int w = 0; w < 8; w++) M = fmaxf(M, s_m[w]);
    const float f = __expf(mw - M);   // this warp's rescale to the common max

    float* sacc = &sx[0][0];          // buf0 free: last tile was (NSUB-1)%3 = 0? no:
                                      // 15%3=0 -> buf0 WAS the last tile; but all
                                      // reads of it completed before the barrier
                                      // above, so overwrite is safe.
    ((float4*)(sacc + warp * D_))[lane]       = make_float4(accA[0]*f, accA[1]*f, accA[2]*f, accA[3]*f);
    ((float4*)(sacc + warp * D_ + 128))[lane] = make_float4(accB[0]*f, accB[1]*f, accB[2]*f, accB[3]*f);
    __syncthreads();

    float o = 0.0f;
    #pragma unroll
    for (int w = 0; w < 8; w++) o += sacc[w * D_ + tid];

    const int idx = b * NCHUNK + c;
    g_pacc[(size_t)idx * D_ + tid] = o;
    if (tid == 0) {
        float Z = 0.0f;
        #pragma unroll
        for (int w = 0; w < 8; w++) Z += s_z[w] * __expf(s_m[w] - M);
        g_pm[idx] = M; g_pz[idx] = Z;
    }
}

// ---------------------------------------------------------------------------
// Kernel 3: merge the NCHUNK chunk partials per batch row, write out[b, d].
// PDL: launches early, waits for k_chunk's grid in-kernel.
// ---------------------------------------------------------------------------
__global__ void k_merge(float* __restrict__ out) {
    cudaGridDependencySynchronize();

    const int b = blockIdx.x;
    const int tid = threadIdx.x;

    float M = -INFINITY;
    #pragma unroll
    for (int c = 0; c < NCHUNK; c++) M = fmaxf(M, g_pm[b * NCHUNK + c]);

    float Z = 0.0f, o = 0.0f;
    #pragma unroll
    for (int c = 0; c < NCHUNK; c++) {
        const float e = __expf(g_pm[b * NCHUNK + c] - M);
        Z += e * g_pz[b * NCHUNK + c];
        o += e * g_pacc[(size_t)(b * NCHUNK + c) * D_ + tid];
    }
    out[b * D_ + tid] = o / Z;
}

// ---------------------------------------------------------------------------
// Inputs (metadata order): 0:x 1:g 2:W 3:Wg 4:b 5:v
// g, Wg, b are provably dead (softmax shift invariance).
// ---------------------------------------------------------------------------
extern "C" void kernel_launch(void* const* d_in, const int* in_sizes, int n_in,
                              void* d_out, int out_size) {
    const float* x = (const float*)d_in[0];
    const float* W = (const float*)d_in[2];
    const float* v = (const float*)d_in[5];
    float* out = (float*)d_out;

    k_wv<<<64, 128>>>(W, v);

    cudaLaunchAttribute pdl[1];
    pdl[0].id = cudaLaunchAttributeProgrammaticStreamSerialization;
    pdl[0].val.programmaticStreamSerializationAllowed = 1;

    cudaLaunchConfig_t cfg1 = {};
    cfg1.gridDim  = dim3(NCHUNK, B_);
    cfg1.blockDim = dim3(256);
    cfg1.stream = 0;
    cfg1.attrs = pdl;
    cfg1.numAttrs = 1;
    cudaLaunchKernelEx(&cfg1, k_chunk, x);

    cudaLaunchConfig_t cfg2 = {};
    cfg2.gridDim  = dim3(B_);
    cfg2.blockDim = dim3(256);
    cfg2.stream = 0;
    cfg2.attrs = pdl;
    cfg2.numAttrs = 1;
    cudaLaunchKernelEx(&cfg2, k_merge, out);
}